// round 14
// baseline (speedup 1.0000x reference)
#include <cuda_runtime.h>
#include <cuda_bf16.h>
#include <cstdint>

// GraphConv: out = segment_sum(feat[src] -> dst) @ W_neigh + b_neigh + feat @ W_self
// N = 100000 nodes, D = 128, E = 600000 edges.
// Harness downcasts int64 indices to int32 — src/dst are const int*.
// SINGLE STREAM ONLY (R11: side-stream forks are dropped by harness capture).
// R14: scatter-atomics replaced by on-the-fly CSR build + gather aggregation.

#define D_FEAT 128
#define N_NODES_MAX 100000
#define N_EDGES_MAX 600000

// Aggregation scratch (51.2 MB) + CSR scratch. Device globals = no allocation.
__device__ float4 g_agg4[(size_t)N_NODES_MAX * (D_FEAT / 4)];
__device__ int g_deg[N_NODES_MAX];
__device__ int g_cursor[N_NODES_MAX];
__device__ int g_off[N_NODES_MAX + 1];
__device__ int g_csr[N_EDGES_MAX];

#define ASTRIDE 136                        // bf16 elems per padded row (272 B)
#define BLK_M 64                           // output rows per CTA (2 CTAs/SM)
#define A_TILE_ELEMS (BLK_M * ASTRIDE)
#define W_TILE_ELEMS (128 * ASTRIDE)
#define W_TILE_U4 (W_TILE_ELEMS * 2 * 2 / 16)  // hi+lo = 4352 uint4
#define GEMM_SMEM_BYTES ((2 * A_TILE_ELEMS + 2 * W_TILE_ELEMS) * 2)  // 104448 B

// Pre-converted weights, padded layout [128][ASTRIDE]: first half hi, then lo.
__device__ uint4 g_Wn_hilo[W_TILE_U4];
__device__ uint4 g_Ws_hilo[W_TILE_U4];

// ---------------------------------------------------------------------------
// helpers
// ---------------------------------------------------------------------------
__device__ __forceinline__ uint32_t smem_u32(const void* p) {
    return (uint32_t)__cvta_generic_to_shared(p);
}
__device__ __forceinline__ void ldm_x4(uint32_t* r, uint32_t addr) {
    asm volatile("ldmatrix.sync.aligned.m8n8.x4.shared.b16 {%0,%1,%2,%3}, [%4];"
                 : "=r"(r[0]), "=r"(r[1]), "=r"(r[2]), "=r"(r[3]) : "r"(addr));
}
__device__ __forceinline__ void ldm_x4_trans(uint32_t* r, uint32_t addr) {
    asm volatile("ldmatrix.sync.aligned.m8n8.x4.trans.shared.b16 {%0,%1,%2,%3}, [%4];"
                 : "=r"(r[0]), "=r"(r[1]), "=r"(r[2]), "=r"(r[3]) : "r"(addr));
}
__device__ __forceinline__ void mma16816(float* c, const uint32_t* a, const uint32_t* b) {
    asm volatile("mma.sync.aligned.m16n8k16.row.col.f32.bf16.bf16.f32 "
                 "{%0,%1,%2,%3}, {%4,%5,%6,%7}, {%8,%9}, {%0,%1,%2,%3};"
                 : "+f"(c[0]), "+f"(c[1]), "+f"(c[2]), "+f"(c[3])
                 : "r"(a[0]), "r"(a[1]), "r"(a[2]), "r"(a[3]), "r"(b[0]), "r"(b[1]));
}
__device__ __forceinline__ uint32_t packbf2(float e0, float e1) {
    uint32_t r;
    asm("cvt.rn.bf16x2.f32 %0, %1, %2;" : "=r"(r) : "f"(e1), "f"(e0));
    return r;
}
__device__ __forceinline__ float bf16_round(float x) {
    return __bfloat162float(__float2bfloat16_rn(x));
}

// ---------------------------------------------------------------------------
// Kernel 0: pre-convert both weight matrices to padded hi/lo bf16 (1 block).
// ---------------------------------------------------------------------------
__global__ void convert_w_kernel(const float* __restrict__ Wn,
                                 const float* __restrict__ Ws) {
    int t = threadIdx.x;
    __nv_bfloat16* nh = reinterpret_cast<__nv_bfloat16*>(g_Wn_hilo);
    __nv_bfloat16* nl = nh + W_TILE_ELEMS;
    __nv_bfloat16* sh = reinterpret_cast<__nv_bfloat16*>(g_Ws_hilo);
    __nv_bfloat16* sl = sh + W_TILE_ELEMS;
#pragma unroll 4
    for (int i = 0; i < 16; ++i) {
        int idx4 = i * 256 + t;
        int row = idx4 >> 5;
        int col = (idx4 & 31) << 2;
        int so = row * ASTRIDE + col;

        float4 w = *reinterpret_cast<const float4*>(Wn + (size_t)row * 128 + col);
        float h0 = bf16_round(w.x), h1 = bf16_round(w.y);
        float h2 = bf16_round(w.z), h3 = bf16_round(w.w);
        *reinterpret_cast<uint2*>(nh + so) = make_uint2(packbf2(h0, h1), packbf2(h2, h3));
        *reinterpret_cast<uint2*>(nl + so) =
            make_uint2(packbf2(w.x - h0, w.y - h1), packbf2(w.z - h2, w.w - h3));

        float4 v = *reinterpret_cast<const float4*>(Ws + (size_t)row * 128 + col);
        float g0 = bf16_round(v.x), g1 = bf16_round(v.y);
        float g2 = bf16_round(v.z), g3 = bf16_round(v.w);
        *reinterpret_cast<uint2*>(sh + so) = make_uint2(packbf2(g0, g1), packbf2(g2, g3));
        *reinterpret_cast<uint2*>(sl + so) =
            make_uint2(packbf2(v.x - g0, v.y - g1), packbf2(v.z - g2, v.w - g3));
    }
}

// ---------------------------------------------------------------------------
// CSR build: zero counters -> histogram -> scan -> fill.
// ---------------------------------------------------------------------------
__global__ void zero_counts_kernel(int n_nodes) {
    int i = blockIdx.x * blockDim.x + threadIdx.x;
    if (i < n_nodes) {
        g_deg[i] = 0;
        g_cursor[i] = 0;
    }
}

__global__ void hist_kernel(const int* __restrict__ dst, int n_edges, int n_nodes) {
    int e = blockIdx.x * blockDim.x + threadIdx.x;
    if (e >= n_edges) return;
    int d = dst[e];
    if ((unsigned)d < (unsigned)n_nodes) atomicAdd(&g_deg[d], 1);
}

// Single-block exclusive scan over n_nodes counts (1024 threads, 2-level).
__global__ void scan_kernel(int n_nodes) {
    __shared__ int chunk_sums[1024];
    __shared__ int warp_sums[32];
    int tid = threadIdx.x;
    int per = (n_nodes + 1023) / 1024;
    int beg = tid * per;
    int end = min(beg + per, n_nodes);

    int s = 0;
    for (int i = beg; i < end; ++i) s += g_deg[i];
    chunk_sums[tid] = s;
    __syncthreads();

    // scan chunk_sums (inclusive within warp via shfl, then warp offsets)
    int lane = tid & 31, wid = tid >> 5;
    int v = chunk_sums[tid];
    int inc = v;
#pragma unroll
    for (int o = 1; o < 32; o <<= 1) {
        int t = __shfl_up_sync(0xffffffffu, inc, o);
        if (lane >= o) inc += t;
    }
    if (lane == 31) warp_sums[wid] = inc;
    __syncthreads();
    if (wid == 0) {
        int w = (lane < 32) ? warp_sums[lane] : 0;
        int wi = w;
#pragma unroll
        for (int o = 1; o < 32; o <<= 1) {
            int t = __shfl_up_sync(0xffffffffu, wi, o);
            if (lane >= o) wi += t;
        }
        warp_sums[lane] = wi - w;   // exclusive warp offsets
    }
    __syncthreads();
    int chunk_excl = inc - v + warp_sums[wid];  // exclusive prefix of this chunk

    // write exclusive offsets for this thread's chunk
    int run = chunk_excl;
    for (int i = beg; i < end; ++i) {
        int d = g_deg[i];
        g_off[i] = run;
        run += d;
    }
    if (end == n_nodes && end > beg) g_off[n_nodes] = run;
    if (tid == 1023 && beg >= n_nodes) g_off[n_nodes] = chunk_excl;  // safety
}

__global__ void fill_kernel(const int* __restrict__ src,
                            const int* __restrict__ dst,
                            int n_edges, int n_nodes) {
    int e = blockIdx.x * blockDim.x + threadIdx.x;
    if (e >= n_edges) return;
    int s = src[e];
    int d = dst[e];
    if ((unsigned)s >= (unsigned)n_nodes || (unsigned)d >= (unsigned)n_nodes) return;
    int pos = g_off[d] + atomicAdd(&g_cursor[d], 1);
    if (pos < N_EDGES_MAX) g_csr[pos] = s;
}

// ---------------------------------------------------------------------------
// Gather aggregation: one warp per node, 4-edge unrolled, one store per row.
// ---------------------------------------------------------------------------
__global__ void gather_kernel(const float* __restrict__ feat, int n_nodes) {
    int node = blockIdx.x * (blockDim.x >> 5) + (threadIdx.x >> 5);
    if (node >= n_nodes) return;
    int lane = threadIdx.x & 31;

    int beg = g_off[node];
    int end = g_off[node + 1];
    const float4* f4 = reinterpret_cast<const float4*>(feat);

    float4 acc = make_float4(0.f, 0.f, 0.f, 0.f);
    int i = beg;
    for (; i + 4 <= end; i += 4) {
        int s0 = g_csr[i + 0];
        int s1 = g_csr[i + 1];
        int s2 = g_csr[i + 2];
        int s3 = g_csr[i + 3];
        float4 v0 = f4[(size_t)s0 * 32 + lane];
        float4 v1 = f4[(size_t)s1 * 32 + lane];
        float4 v2 = f4[(size_t)s2 * 32 + lane];
        float4 v3 = f4[(size_t)s3 * 32 + lane];
        acc.x += (v0.x + v1.x) + (v2.x + v3.x);
        acc.y += (v0.y + v1.y) + (v2.y + v3.y);
        acc.z += (v0.z + v1.z) + (v2.z + v3.z);
        acc.w += (v0.w + v1.w) + (v2.w + v3.w);
    }
    for (; i < end; ++i) {
        int s = g_csr[i];
        float4 v = f4[(size_t)s * 32 + lane];
        acc.x += v.x; acc.y += v.y; acc.z += v.z; acc.w += v.w;
    }
    g_agg4[(size_t)node * 32 + lane] = acc;
}

// ---------------------------------------------------------------------------
// Fused dual split-bf16 tensor-core GEMM + bias (unchanged from R13).
// ---------------------------------------------------------------------------
__global__ __launch_bounds__(256, 2)
void gemm_kernel(const float* __restrict__ feat,
                 const float* __restrict__ bn,
                 float* __restrict__ out,
                 int n_nodes) {
    extern __shared__ char smem[];
    __nv_bfloat16* Ahi = reinterpret_cast<__nv_bfloat16*>(smem);
    __nv_bfloat16* Alo = Ahi + A_TILE_ELEMS;
    __nv_bfloat16* Whi = Alo + A_TILE_ELEMS;

    const uint32_t aHi_b = smem_u32(Ahi);
    const uint32_t aLo_b = smem_u32(Alo);
    const uint32_t wHi_b = smem_u32(Whi);
    const uint32_t wLo_b = wHi_b + W_TILE_ELEMS * 2;

    int tid = threadIdx.x;
    int lane = tid & 31;
    int wid = tid >> 5;
    int wm = wid & 1;
    int wn = wid >> 1;
    int m0 = blockIdx.x * BLK_M;

    int lrow = lane & 15;
    int lcolh = (lane >> 4) << 3;

    const float* aggf = reinterpret_cast<const float*>(g_agg4);

    float acc[2][4][4];
#pragma unroll
    for (int mi = 0; mi < 2; mi++)
#pragma unroll
        for (int ni = 0; ni < 4; ni++)
#pragma unroll
            for (int q = 0; q < 4; q++)
                acc[mi][ni][q] = 0.f;

    for (int half = 0; half < 2; ++half) {
        const float* Aglob = half ? feat : aggf;
        const uint4* Wsrc = half ? g_Ws_hilo : g_Wn_hilo;

        __syncthreads();

        {
            uint4* wdst = reinterpret_cast<uint4*>(Whi);
#pragma unroll
            for (int i = 0; i < 17; ++i) {
                int idx = i * 256 + tid;
                wdst[idx] = Wsrc[idx];
            }
        }

#pragma unroll
        for (int it = 0; it < 8; ++it) {
            int idx4 = it * 256 + tid;
            int row = idx4 >> 5;
            int col = (idx4 & 31) << 2;

            int grow = m0 + row;
            if (grow >= n_nodes) grow = n_nodes - 1;
            float4 v = *reinterpret_cast<const float4*>(Aglob + (size_t)grow * 128 + col);
            float h0 = bf16_round(v.x), h1 = bf16_round(v.y);
            float h2 = bf16_round(v.z), h3 = bf16_round(v.w);
            int so = row * ASTRIDE + col;
            *reinterpret_cast<uint2*>(Ahi + so) = make_uint2(packbf2(h0, h1), packbf2(h2, h3));
            *reinterpret_cast<uint2*>(Alo + so) =
                make_uint2(packbf2(v.x - h0, v.y - h1), packbf2(v.z - h2, v.w - h3));
        }
        __syncthreads();

#pragma unroll
        for (int ks = 0; ks < 8; ++ks) {
            int k0 = ks * 16;

            uint32_t ahi[2][4], alo[2][4];
#pragma unroll
            for (int mi = 0; mi < 2; ++mi) {
                uint32_t off = (uint32_t)((wm * 32 + mi * 16 + lrow) * ASTRIDE + k0 + lcolh) * 2;
                ldm_x4(ahi[mi], aHi_b + off);
                ldm_x4(alo[mi], aLo_b + off);
            }
            uint32_t bhi[4][2], blo[4][2];
#pragma unroll
            for (int nh = 0; nh < 2; ++nh) {
                uint32_t off = (uint32_t)((k0 + lrow) * ASTRIDE + wn * 32 + nh * 16 + lcolh) * 2;
                uint32_t t[4];
                ldm_x4_trans(t, wHi_b + off);
                bhi[2 * nh][0] = t[0]; bhi[2 * nh][1] = t[1];
                bhi[2 * nh + 1][0] = t[2]; bhi[2 * nh + 1][1] = t[3];
                ldm_x4_trans(t, wLo_b + off);
                blo[2 * nh][0] = t[0]; blo[2 * nh][1] = t[1];
                blo[2 * nh + 1][0] = t[2]; blo[2 * nh + 1][1] = t[3];
            }
#pragma unroll
            for (int mi = 0; mi < 2; ++mi)
#pragma unroll
                for (int ni = 0; ni < 4; ++ni) {
                    mma16816(acc[mi][ni], ahi[mi], bhi[ni]);
                    mma16816(acc[mi][ni], ahi[mi], blo[ni]);
                    mma16816(acc[mi][ni], alo[mi], bhi[ni]);
                }
        }
    }

    int g = lane >> 2, tg = lane & 3;
#pragma unroll
    for (int ni = 0; ni < 4; ++ni) {
        int col = wn * 32 + ni * 8 + 2 * tg;
        float2 bv = *reinterpret_cast<const float2*>(bn + col);
#pragma unroll
        for (int mi = 0; mi < 2; ++mi) {
            int r0 = m0 + wm * 32 + mi * 16 + g;
            if (r0 < n_nodes) {
                float2 o = make_float2(acc[mi][ni][0] + bv.x, acc[mi][ni][1] + bv.y);
                *reinterpret_cast<float2*>(out + (size_t)r0 * 128 + col) = o;
            }
            int r1 = r0 + 8;
            if (r1 < n_nodes) {
                float2 o = make_float2(acc[mi][ni][2] + bv.x, acc[mi][ni][3] + bv.y);
                *reinterpret_cast<float2*>(out + (size_t)r1 * 128 + col) = o;
            }
        }
    }
}

// ---------------------------------------------------------------------------
// Launch (single stream, strictly serial — capture-safe).
// ---------------------------------------------------------------------------
extern "C" void kernel_launch(void* const* d_in, const int* in_sizes, int n_in,
                              void* d_out, int out_size) {
    const float* feat = (const float*)d_in[0];
    const int* src    = (const int*)d_in[1];   // int64 downcast to int32 by harness
    const int* dst    = (const int*)d_in[2];
    const float* Wn   = (const float*)d_in[3];
    const float* bn   = (const float*)d_in[4];
    const float* Ws   = (const float*)d_in[5];
    float* out        = (float*)d_out;

    int n_nodes = in_sizes[0] / D_FEAT;
    int n_edges = in_sizes[1];
    if (n_edges > N_EDGES_MAX) n_edges = N_EDGES_MAX;

    static bool attr_set = false;
    if (!attr_set) {
        cudaFuncSetAttribute(gemm_kernel,
                             cudaFuncAttributeMaxDynamicSharedMemorySize,
                             GEMM_SMEM_BYTES);
        attr_set = true;
    }

    // 0) pre-convert weights (1 block) — independent of CSR path
    convert_w_kernel<<<1, 256>>>(Wn, Ws);

    // 1) CSR build
    zero_counts_kernel<<<(n_nodes + 255) / 256, 256>>>(n_nodes);
    hist_kernel<<<(n_edges + 255) / 256, 256>>>(dst, n_edges, n_nodes);
    scan_kernel<<<1, 1024>>>(n_nodes);
    fill_kernel<<<(n_edges + 255) / 256, 256>>>(src, dst, n_edges, n_nodes);

    // 2) gather aggregation (8 warps per block, one warp per node)
    int gb = (n_nodes + 7) / 8;
    gather_kernel<<<gb, 256>>>(feat, n_nodes);

    // 3) fused dual GEMM + bias (64-row tiles, 2 CTAs/SM)
    int gblocks = (n_nodes + BLK_M - 1) / BLK_M;
    gemm_kernel<<<gblocks, 256, GEMM_SMEM_BYTES>>>(feat, bn, out, n_nodes);
}

// round 15
// speedup vs baseline: 1.6229x; 1.6229x over previous
#include <cuda_runtime.h>
#include <cuda_bf16.h>
#include <cstdint>

// GraphConv: out = segment_sum(feat[src] -> dst) @ W_neigh + b_neigh + feat @ W_self
// N = 100000 nodes, D = 128, E = 600000 edges.
// Harness downcasts int64 indices to int32 — src/dst are const int*.
// SINGLE STREAM ONLY (R11: side-stream forks are dropped by harness capture).
// R15: parallel 3-phase scan (R14's 1-block scan cost 95.8us on its own).

#define D_FEAT 128
#define N_NODES_MAX 100000
#define N_EDGES_MAX 600000
#define SCAN_CHUNK 256
#define SCAN_NB ((N_NODES_MAX + SCAN_CHUNK - 1) / SCAN_CHUNK)   // 391

// Aggregation scratch (51.2 MB) + CSR scratch. Device globals = no allocation.
__device__ float4 g_agg4[(size_t)N_NODES_MAX * (D_FEAT / 4)];
__device__ int g_deg[N_NODES_MAX];
__device__ int g_cursor[N_NODES_MAX];
__device__ int g_off[N_NODES_MAX + 1];
__device__ int g_csr[N_EDGES_MAX];
__device__ int g_bsum[SCAN_NB];
__device__ int g_boff[SCAN_NB];

#define ASTRIDE 136                        // bf16 elems per padded row (272 B)
#define BLK_M 64                           // output rows per CTA (2 CTAs/SM)
#define A_TILE_ELEMS (BLK_M * ASTRIDE)
#define W_TILE_ELEMS (128 * ASTRIDE)
#define W_TILE_U4 (W_TILE_ELEMS * 2 * 2 / 16)  // hi+lo = 4352 uint4
#define GEMM_SMEM_BYTES ((2 * A_TILE_ELEMS + 2 * W_TILE_ELEMS) * 2)  // 104448 B

// Pre-converted weights, padded layout [128][ASTRIDE]: first half hi, then lo.
__device__ uint4 g_Wn_hilo[W_TILE_U4];
__device__ uint4 g_Ws_hilo[W_TILE_U4];

// ---------------------------------------------------------------------------
// helpers
// ---------------------------------------------------------------------------
__device__ __forceinline__ uint32_t smem_u32(const void* p) {
    return (uint32_t)__cvta_generic_to_shared(p);
}
__device__ __forceinline__ void ldm_x4(uint32_t* r, uint32_t addr) {
    asm volatile("ldmatrix.sync.aligned.m8n8.x4.shared.b16 {%0,%1,%2,%3}, [%4];"
                 : "=r"(r[0]), "=r"(r[1]), "=r"(r[2]), "=r"(r[3]) : "r"(addr));
}
__device__ __forceinline__ void ldm_x4_trans(uint32_t* r, uint32_t addr) {
    asm volatile("ldmatrix.sync.aligned.m8n8.x4.trans.shared.b16 {%0,%1,%2,%3}, [%4];"
                 : "=r"(r[0]), "=r"(r[1]), "=r"(r[2]), "=r"(r[3]) : "r"(addr));
}
__device__ __forceinline__ void mma16816(float* c, const uint32_t* a, const uint32_t* b) {
    asm volatile("mma.sync.aligned.m16n8k16.row.col.f32.bf16.bf16.f32 "
                 "{%0,%1,%2,%3}, {%4,%5,%6,%7}, {%8,%9}, {%0,%1,%2,%3};"
                 : "+f"(c[0]), "+f"(c[1]), "+f"(c[2]), "+f"(c[3])
                 : "r"(a[0]), "r"(a[1]), "r"(a[2]), "r"(a[3]), "r"(b[0]), "r"(b[1]));
}
__device__ __forceinline__ uint32_t packbf2(float e0, float e1) {
    uint32_t r;
    asm("cvt.rn.bf16x2.f32 %0, %1, %2;" : "=r"(r) : "f"(e1), "f"(e0));
    return r;
}
__device__ __forceinline__ float bf16_round(float x) {
    return __bfloat162float(__float2bfloat16_rn(x));
}

// ---------------------------------------------------------------------------
// Kernel 0: pre-convert both weight matrices to padded hi/lo bf16 (1 block).
// ---------------------------------------------------------------------------
__global__ void convert_w_kernel(const float* __restrict__ Wn,
                                 const float* __restrict__ Ws) {
    int t = threadIdx.x;
    __nv_bfloat16* nh = reinterpret_cast<__nv_bfloat16*>(g_Wn_hilo);
    __nv_bfloat16* nl = nh + W_TILE_ELEMS;
    __nv_bfloat16* sh = reinterpret_cast<__nv_bfloat16*>(g_Ws_hilo);
    __nv_bfloat16* sl = sh + W_TILE_ELEMS;
#pragma unroll 4
    for (int i = 0; i < 16; ++i) {
        int idx4 = i * 256 + t;
        int row = idx4 >> 5;
        int col = (idx4 & 31) << 2;
        int so = row * ASTRIDE + col;

        float4 w = *reinterpret_cast<const float4*>(Wn + (size_t)row * 128 + col);
        float h0 = bf16_round(w.x), h1 = bf16_round(w.y);
        float h2 = bf16_round(w.z), h3 = bf16_round(w.w);
        *reinterpret_cast<uint2*>(nh + so) = make_uint2(packbf2(h0, h1), packbf2(h2, h3));
        *reinterpret_cast<uint2*>(nl + so) =
            make_uint2(packbf2(w.x - h0, w.y - h1), packbf2(w.z - h2, w.w - h3));

        float4 v = *reinterpret_cast<const float4*>(Ws + (size_t)row * 128 + col);
        float g0 = bf16_round(v.x), g1 = bf16_round(v.y);
        float g2 = bf16_round(v.z), g3 = bf16_round(v.w);
        *reinterpret_cast<uint2*>(sh + so) = make_uint2(packbf2(g0, g1), packbf2(g2, g3));
        *reinterpret_cast<uint2*>(sl + so) =
            make_uint2(packbf2(v.x - g0, v.y - g1), packbf2(v.z - g2, v.w - g3));
    }
}

// ---------------------------------------------------------------------------
// CSR build: zero -> histogram -> 3-phase parallel scan -> fill.
// ---------------------------------------------------------------------------
__global__ void zero_counts_kernel(int n_nodes) {
    int i = blockIdx.x * blockDim.x + threadIdx.x;
    if (i < n_nodes) {
        g_deg[i] = 0;
        g_cursor[i] = 0;
    }
}

__global__ void hist_kernel(const int* __restrict__ dst, int n_edges, int n_nodes) {
    int e = blockIdx.x * blockDim.x + threadIdx.x;
    if (e >= n_edges) return;
    int d = dst[e];
    if ((unsigned)d < (unsigned)n_nodes) atomicAdd(&g_deg[d], 1);
}

// Phase 1: per-block (256-node chunk) degree sums.
__global__ void block_sum_kernel(int n_nodes) {
    __shared__ int warp_sums[8];
    int b = blockIdx.x;
    int i = b * SCAN_CHUNK + threadIdx.x;
    int v = (i < n_nodes) ? g_deg[i] : 0;
    int lane = threadIdx.x & 31, wid = threadIdx.x >> 5;
#pragma unroll
    for (int o = 16; o > 0; o >>= 1) v += __shfl_down_sync(0xffffffffu, v, o);
    if (lane == 0) warp_sums[wid] = v;
    __syncthreads();
    if (threadIdx.x == 0) {
        int s = 0;
#pragma unroll
        for (int w = 0; w < 8; ++w) s += warp_sums[w];
        g_bsum[b] = s;
    }
}

// Phase 2: single block scans the 391 block sums (smem-resident, fast).
__global__ void scan_bsums_kernel(int nb, int n_nodes) {
    __shared__ int warp_sums[16];
    int tid = threadIdx.x;           // 512 threads
    int lane = tid & 31, wid = tid >> 5;
    int v = (tid < nb) ? g_bsum[tid] : 0;
    int inc = v;
#pragma unroll
    for (int o = 1; o < 32; o <<= 1) {
        int t = __shfl_up_sync(0xffffffffu, inc, o);
        if (lane >= o) inc += t;
    }
    if (lane == 31) warp_sums[wid] = inc;
    __syncthreads();
    if (wid == 0 && lane < 16) {
        int w = warp_sums[lane];
        int wi = w;
#pragma unroll
        for (int o = 1; o < 16; o <<= 1) {
            int t = __shfl_up_sync(0xffffu, wi, o);
            if (lane >= o) wi += t;
        }
        warp_sums[lane] = wi - w;    // exclusive warp offsets
    }
    __syncthreads();
    int excl = inc - v + warp_sums[wid];
    if (tid < nb) g_boff[tid] = excl;
    if (tid == nb - 1) g_off[n_nodes] = excl + v;   // grand total
}

// Phase 3: per-block exclusive scan of 256 degrees + block offset.
__global__ void write_offsets_kernel(int n_nodes) {
    __shared__ int warp_sums[8];
    int b = blockIdx.x;
    int i = b * SCAN_CHUNK + threadIdx.x;
    int lane = threadIdx.x & 31, wid = threadIdx.x >> 5;
    int v = (i < n_nodes) ? g_deg[i] : 0;
    int inc = v;
#pragma unroll
    for (int o = 1; o < 32; o <<= 1) {
        int t = __shfl_up_sync(0xffffffffu, inc, o);
        if (lane >= o) inc += t;
    }
    if (lane == 31) warp_sums[wid] = inc;
    __syncthreads();
    if (wid == 0 && lane < 8) {
        int w = warp_sums[lane];
        int wi = w;
#pragma unroll
        for (int o = 1; o < 8; o <<= 1) {
            int t = __shfl_up_sync(0xffu, wi, o);
            if (lane >= o) wi += t;
        }
        warp_sums[lane] = wi - w;
    }
    __syncthreads();
    if (i < n_nodes) g_off[i] = g_boff[b] + (inc - v) + warp_sums[wid];
}

__global__ void fill_kernel(const int* __restrict__ src,
                            const int* __restrict__ dst,
                            int n_edges, int n_nodes) {
    int e = blockIdx.x * blockDim.x + threadIdx.x;
    if (e >= n_edges) return;
    int s = src[e];
    int d = dst[e];
    if ((unsigned)s >= (unsigned)n_nodes || (unsigned)d >= (unsigned)n_nodes) return;
    int pos = g_off[d] + atomicAdd(&g_cursor[d], 1);
    if (pos < N_EDGES_MAX) g_csr[pos] = s;
}

// ---------------------------------------------------------------------------
// Gather aggregation: one warp per node, 4-edge unrolled, one store per row.
// ---------------------------------------------------------------------------
__global__ void gather_kernel(const float* __restrict__ feat, int n_nodes) {
    int node = blockIdx.x * (blockDim.x >> 5) + (threadIdx.x >> 5);
    if (node >= n_nodes) return;
    int lane = threadIdx.x & 31;

    int beg = g_off[node];
    int end = g_off[node + 1];
    const float4* f4 = reinterpret_cast<const float4*>(feat);

    float4 acc = make_float4(0.f, 0.f, 0.f, 0.f);
    int i = beg;
    for (; i + 4 <= end; i += 4) {
        int s0 = g_csr[i + 0];
        int s1 = g_csr[i + 1];
        int s2 = g_csr[i + 2];
        int s3 = g_csr[i + 3];
        float4 v0 = f4[(size_t)s0 * 32 + lane];
        float4 v1 = f4[(size_t)s1 * 32 + lane];
        float4 v2 = f4[(size_t)s2 * 32 + lane];
        float4 v3 = f4[(size_t)s3 * 32 + lane];
        acc.x += (v0.x + v1.x) + (v2.x + v3.x);
        acc.y += (v0.y + v1.y) + (v2.y + v3.y);
        acc.z += (v0.z + v1.z) + (v2.z + v3.z);
        acc.w += (v0.w + v1.w) + (v2.w + v3.w);
    }
    for (; i < end; ++i) {
        int s = g_csr[i];
        float4 v = f4[(size_t)s * 32 + lane];
        acc.x += v.x; acc.y += v.y; acc.z += v.z; acc.w += v.w;
    }
    g_agg4[(size_t)node * 32 + lane] = acc;
}

// ---------------------------------------------------------------------------
// Fused dual split-bf16 tensor-core GEMM + bias (unchanged from R13).
// ---------------------------------------------------------------------------
__global__ __launch_bounds__(256, 2)
void gemm_kernel(const float* __restrict__ feat,
                 const float* __restrict__ bn,
                 float* __restrict__ out,
                 int n_nodes) {
    extern __shared__ char smem[];
    __nv_bfloat16* Ahi = reinterpret_cast<__nv_bfloat16*>(smem);
    __nv_bfloat16* Alo = Ahi + A_TILE_ELEMS;
    __nv_bfloat16* Whi = Alo + A_TILE_ELEMS;

    const uint32_t aHi_b = smem_u32(Ahi);
    const uint32_t aLo_b = smem_u32(Alo);
    const uint32_t wHi_b = smem_u32(Whi);
    const uint32_t wLo_b = wHi_b + W_TILE_ELEMS * 2;

    int tid = threadIdx.x;
    int lane = tid & 31;
    int wid = tid >> 5;
    int wm = wid & 1;
    int wn = wid >> 1;
    int m0 = blockIdx.x * BLK_M;

    int lrow = lane & 15;
    int lcolh = (lane >> 4) << 3;

    const float* aggf = reinterpret_cast<const float*>(g_agg4);

    float acc[2][4][4];
#pragma unroll
    for (int mi = 0; mi < 2; mi++)
#pragma unroll
        for (int ni = 0; ni < 4; ni++)
#pragma unroll
            for (int q = 0; q < 4; q++)
                acc[mi][ni][q] = 0.f;

    for (int half = 0; half < 2; ++half) {
        const float* Aglob = half ? feat : aggf;
        const uint4* Wsrc = half ? g_Ws_hilo : g_Wn_hilo;

        __syncthreads();

        {
            uint4* wdst = reinterpret_cast<uint4*>(Whi);
#pragma unroll
            for (int i = 0; i < 17; ++i) {
                int idx = i * 256 + tid;
                wdst[idx] = Wsrc[idx];
            }
        }

#pragma unroll
        for (int it = 0; it < 8; ++it) {
            int idx4 = it * 256 + tid;
            int row = idx4 >> 5;
            int col = (idx4 & 31) << 2;

            int grow = m0 + row;
            if (grow >= n_nodes) grow = n_nodes - 1;
            float4 v = *reinterpret_cast<const float4*>(Aglob + (size_t)grow * 128 + col);
            float h0 = bf16_round(v.x), h1 = bf16_round(v.y);
            float h2 = bf16_round(v.z), h3 = bf16_round(v.w);
            int so = row * ASTRIDE + col;
            *reinterpret_cast<uint2*>(Ahi + so) = make_uint2(packbf2(h0, h1), packbf2(h2, h3));
            *reinterpret_cast<uint2*>(Alo + so) =
                make_uint2(packbf2(v.x - h0, v.y - h1), packbf2(v.z - h2, v.w - h3));
        }
        __syncthreads();

#pragma unroll
        for (int ks = 0; ks < 8; ++ks) {
            int k0 = ks * 16;

            uint32_t ahi[2][4], alo[2][4];
#pragma unroll
            for (int mi = 0; mi < 2; ++mi) {
                uint32_t off = (uint32_t)((wm * 32 + mi * 16 + lrow) * ASTRIDE + k0 + lcolh) * 2;
                ldm_x4(ahi[mi], aHi_b + off);
                ldm_x4(alo[mi], aLo_b + off);
            }
            uint32_t bhi[4][2], blo[4][2];
#pragma unroll
            for (int nh = 0; nh < 2; ++nh) {
                uint32_t off = (uint32_t)((k0 + lrow) * ASTRIDE + wn * 32 + nh * 16 + lcolh) * 2;
                uint32_t t[4];
                ldm_x4_trans(t, wHi_b + off);
                bhi[2 * nh][0] = t[0]; bhi[2 * nh][1] = t[1];
                bhi[2 * nh + 1][0] = t[2]; bhi[2 * nh + 1][1] = t[3];
                ldm_x4_trans(t, wLo_b + off);
                blo[2 * nh][0] = t[0]; blo[2 * nh][1] = t[1];
                blo[2 * nh + 1][0] = t[2]; blo[2 * nh + 1][1] = t[3];
            }
#pragma unroll
            for (int mi = 0; mi < 2; ++mi)
#pragma unroll
                for (int ni = 0; ni < 4; ++ni) {
                    mma16816(acc[mi][ni], ahi[mi], bhi[ni]);
                    mma16816(acc[mi][ni], ahi[mi], blo[ni]);
                    mma16816(acc[mi][ni], alo[mi], bhi[ni]);
                }
        }
    }

    int g = lane >> 2, tg = lane & 3;
#pragma unroll
    for (int ni = 0; ni < 4; ++ni) {
        int col = wn * 32 + ni * 8 + 2 * tg;
        float2 bv = *reinterpret_cast<const float2*>(bn + col);
#pragma unroll
        for (int mi = 0; mi < 2; ++mi) {
            int r0 = m0 + wm * 32 + mi * 16 + g;
            if (r0 < n_nodes) {
                float2 o = make_float2(acc[mi][ni][0] + bv.x, acc[mi][ni][1] + bv.y);
                *reinterpret_cast<float2*>(out + (size_t)r0 * 128 + col) = o;
            }
            int r1 = r0 + 8;
            if (r1 < n_nodes) {
                float2 o = make_float2(acc[mi][ni][2] + bv.x, acc[mi][ni][3] + bv.y);
                *reinterpret_cast<float2*>(out + (size_t)r1 * 128 + col) = o;
            }
        }
    }
}

// ---------------------------------------------------------------------------
// Launch (single stream, strictly serial — capture-safe).
// ---------------------------------------------------------------------------
extern "C" void kernel_launch(void* const* d_in, const int* in_sizes, int n_in,
                              void* d_out, int out_size) {
    const float* feat = (const float*)d_in[0];
    const int* src    = (const int*)d_in[1];   // int64 downcast to int32 by harness
    const int* dst    = (const int*)d_in[2];
    const float* Wn   = (const float*)d_in[3];
    const float* bn   = (const float*)d_in[4];
    const float* Ws   = (const float*)d_in[5];
    float* out        = (float*)d_out;

    int n_nodes = in_sizes[0] / D_FEAT;
    int n_edges = in_sizes[1];
    if (n_edges > N_EDGES_MAX) n_edges = N_EDGES_MAX;

    static bool attr_set = false;
    if (!attr_set) {
        cudaFuncSetAttribute(gemm_kernel,
                             cudaFuncAttributeMaxDynamicSharedMemorySize,
                             GEMM_SMEM_BYTES);
        attr_set = true;
    }

    int nb = (n_nodes + SCAN_CHUNK - 1) / SCAN_CHUNK;

    // 0) pre-convert weights (1 block)
    convert_w_kernel<<<1, 256>>>(Wn, Ws);

    // 1) CSR build (parallel scan: block sums -> scan sums -> write offsets)
    zero_counts_kernel<<<(n_nodes + 255) / 256, 256>>>(n_nodes);
    hist_kernel<<<(n_edges + 255) / 256, 256>>>(dst, n_edges, n_nodes);
    block_sum_kernel<<<nb, SCAN_CHUNK>>>(n_nodes);
    scan_bsums_kernel<<<1, 512>>>(nb, n_nodes);
    write_offsets_kernel<<<nb, SCAN_CHUNK>>>(n_nodes);
    fill_kernel<<<(n_edges + 255) / 256, 256>>>(src, dst, n_edges, n_nodes);

    // 2) gather aggregation (8 warps per block, one warp per node)
    int gb = (n_nodes + 7) / 8;
    gather_kernel<<<gb, 256>>>(feat, n_nodes);

    // 3) fused dual GEMM + bias (64-row tiles, 2 CTAs/SM)
    int gblocks = (n_nodes + BLK_M - 1) / BLK_M;
    gemm_kernel<<<gblocks, 256, GEMM_SMEM_BYTES>>>(feat, bn, out, n_nodes);
}